// round 1
// baseline (speedup 1.0000x reference)
#include <cuda_runtime.h>
#include <math.h>

#define BB 16
#define CIN 20
#define HH 256
#define WW 256
#define WID 64
#define M1V 16
#define M2V 16
#define NLAY 4
#define FCH 128
#define CO 20
#define HW 65536
#define NPIX (BB*HW)

#define TWO_PI 6.28318530717958647692f

// ---------------- scratch (device globals; no allocations allowed) ----------------
__device__ float  g_h0[(size_t)BB*WID*HW];            // 268 MB ping
__device__ float  g_h1[(size_t)BB*WID*HW];            // 268 MB pong
__device__ float2 g_Fw[(size_t)BB*WID*HH*M2V];        // (b,c,h,ky)  33.5 MB
__device__ float2 g_Fm[(size_t)BB*WID*32*M2V];        // (b,c,kxi,ky) 4 MB
__device__ float2 g_Gm[(size_t)BB*WID*32*M2V];        // 4 MB
__device__ float2 g_Gw[(size_t)BB*WID*HH*M2V];        // (b,c,h,ky)  33.5 MB
__device__ float2 g_Wt[(size_t)NLAY*512*WID*WID];     // (l,m,i,o)   67 MB
__device__ float2 g_Tfw[M2V*WW];                      // e^{-2pi i ky w/256}
__device__ float2 g_Tfh[32*HH];                       // e^{-2pi i kx h/256}, kx in R
__device__ float2 g_Tih[32*HH];                       // conj of above

__device__ __forceinline__ float gelu_exact(float v) {
    return 0.5f * v * (1.0f + erff(v * 0.70710678118654752440f));
}

// ---------------- twiddle init ----------------
__global__ void k_twiddle() {
    int idx = blockIdx.x * blockDim.x + threadIdx.x;   // up to 8192
    if (idx < M2V * WW) {
        int ky = idx >> 8, w = idx & 255;
        int ph = (ky * w) & 255;                       // exact phase mod 256
        float s, c;
        sincosf(-TWO_PI * (float)ph * (1.0f / 256.0f), &s, &c);
        g_Tfw[idx] = make_float2(c, s);
    }
    if (idx < 32 * HH) {
        int kxi = idx >> 8, h = idx & 255;
        int kx = (kxi < 16) ? kxi : (224 + kxi);       // rows 240..255
        int ph = (kx * h) & 255;
        float s, c;
        sincosf(-TWO_PI * (float)ph * (1.0f / 256.0f), &s, &c);
        g_Tfh[idx] = make_float2(c, s);
        g_Tih[idx] = make_float2(c, -s);
    }
}

// ---------------- spectral-weight transpose: (l,i,o,kx,ky) -> (l,m,i,o) ----------------
__global__ void k_wt(const float* __restrict__ w1r, const float* __restrict__ w1i,
                     const float* __restrict__ w2r, const float* __restrict__ w2i) {
    int tid = blockIdx.x * blockDim.x + threadIdx.x;
    if (tid >= NLAY * 512 * WID * WID) return;
    int o   = tid & 63;
    int i   = (tid >> 6) & 63;
    int m   = (tid >> 12) & 511;
    int l   = tid >> 21;
    int kxi = m >> 4;
    int ky  = m & 15;
    int kk  = (kxi & 15) * 16 + ky;
    size_t src = ((size_t)(l * 64 + i) * 64 + o) * 256 + kk;
    float r, im;
    if (kxi < 16) { r = w1r[src]; im = w1i[src]; }
    else          { r = w2r[src]; im = w2i[src]; }
    g_Wt[tid] = make_float2(r, im);
}

// ---------------- fc0 lift: 20 -> 64 per pixel ----------------
__global__ void k_fc0(const float* __restrict__ x, const float* __restrict__ w,
                      const float* __restrict__ bias) {
    __shared__ float ws[WID * CIN];
    __shared__ float bs[WID];
    int t = threadIdx.x;
    for (int k = t; k < WID * CIN; k += 256) ws[k] = w[k];
    if (t < WID) bs[t] = bias[t];
    __syncthreads();
    int p  = blockIdx.x * 256 + t;
    int b  = p >> 16;
    int sp = p & 65535;
    float xr[CIN];
#pragma unroll
    for (int c = 0; c < CIN; c++) xr[c] = x[((size_t)(b * CIN + c) << 16) + sp];
#pragma unroll
    for (int d = 0; d < WID; d++) {
        float a = bs[d];
#pragma unroll
        for (int c = 0; c < CIN; c++) a = fmaf(xr[c], ws[d * CIN + c], a);
        g_h0[((size_t)(b * WID + d) << 16) + sp] = a;
    }
}

// ---------------- forward DFT along w: one warp per (b,c,h) row ----------------
__global__ void k_dftw(const float* __restrict__ hin) {
    __shared__ float2 T[M2V * WW];                    // 32 KB
    int t = threadIdx.x;
    for (int k = t; k < M2V * WW; k += 256) T[k] = g_Tfw[k];
    __syncthreads();
    int warp = t >> 5, lane = t & 31;
    int r = blockIdx.x * 8 + warp;                    // r < 262144
    const float* row = hin + (size_t)r * 256;
    float ar[16], ai[16];
#pragma unroll
    for (int k = 0; k < 16; k++) { ar[k] = 0.f; ai[k] = 0.f; }
    for (int j = 0; j < 8; j++) {
        int w = lane + j * 32;
        float v = row[w];
#pragma unroll
        for (int ky = 0; ky < 16; ky++) {
            float2 tw = T[ky * 256 + w];
            ar[ky] = fmaf(v, tw.x, ar[ky]);
            ai[ky] = fmaf(v, tw.y, ai[ky]);
        }
    }
#pragma unroll
    for (int off = 16; off; off >>= 1) {
#pragma unroll
        for (int k = 0; k < 16; k++) {
            ar[k] += __shfl_xor_sync(0xffffffffu, ar[k], off);
            ai[k] += __shfl_xor_sync(0xffffffffu, ai[k], off);
        }
    }
    if (lane == 0) {
#pragma unroll
        for (int k = 0; k < 16; k++)
            g_Fw[(size_t)r * 16 + k] = make_float2(ar[k], ai[k]);
    }
}

// ---------------- forward DFT along h: block per (b,c) ----------------
__global__ void k_dfth() {
    extern __shared__ float2 sh[];
    float2* Fsh = sh;            // 4096 = 256*16
    float2* Tsh = sh + 4096;     // 8192 = 32*256
    int t = threadIdx.x;
    int bc = blockIdx.x;
    for (int k = t; k < 4096; k += 256) Fsh[k] = g_Fw[(size_t)bc * 4096 + k];
    for (int k = t; k < 8192; k += 256) Tsh[k] = g_Tfh[k];
    __syncthreads();
#pragma unroll
    for (int mm = 0; mm < 2; mm++) {
        int m = t + mm * 256;
        int kxi = m >> 4, ky = m & 15;
        float sr = 0.f, si = 0.f;
        for (int h = 0; h < 256; h++) {
            float2 f  = Fsh[h * 16 + ky];
            float2 tw = Tsh[kxi * 256 + h];
            sr = fmaf(f.x, tw.x, fmaf(-f.y, tw.y, sr));
            si = fmaf(f.x, tw.y, fmaf( f.y, tw.x, si));
        }
        g_Fm[(size_t)bc * 512 + m] = make_float2(sr, si);
    }
}

// ---------------- channel mixing: block per mode ----------------
__global__ void k_mix(int layer) {
    __shared__ float2 Wm[WID * WID];   // 32 KB
    __shared__ float2 Fsh[BB * WID];   //  8 KB
    int t = threadIdx.x;
    int m = blockIdx.x;
    const float2* wsrc = g_Wt + ((size_t)layer * 512 + m) * 4096;
    for (int k = t; k < 4096; k += 256) Wm[k] = wsrc[k];
    for (int k = t; k < 1024; k += 256) {
        int b = k >> 6, i = k & 63;
        Fsh[k] = g_Fm[(size_t)(b * 64 + i) * 512 + m];
    }
    __syncthreads();
#pragma unroll
    for (int u = 0; u < 4; u++) {
        int outi = t + u * 256;
        int b = outi >> 6, o = outi & 63;
        float sr = 0.f, si = 0.f;
#pragma unroll 8
        for (int i = 0; i < 64; i++) {
            float2 f = Fsh[b * 64 + i];
            float2 w = Wm[i * 64 + o];
            sr = fmaf(f.x, w.x, fmaf(-f.y, w.y, sr));
            si = fmaf(f.x, w.y, fmaf( f.y, w.x, si));
        }
        g_Gm[(size_t)(b * 64 + o) * 512 + m] = make_float2(sr, si);
    }
}

// ---------------- inverse transform along h: block per (b,c) ----------------
__global__ void k_idfth() {
    extern __shared__ float2 sh[];
    float2* Gsh = sh;            // 512
    float2* Tsh = sh + 512;      // 8192
    int t = threadIdx.x;
    int bc = blockIdx.x;
    for (int k = t; k < 512; k += 256) Gsh[k] = g_Gm[(size_t)bc * 512 + k];
    for (int k = t; k < 8192; k += 256) Tsh[k] = g_Tih[k];
    __syncthreads();
    int h = t;
    float orr[16], oii[16];
#pragma unroll
    for (int k = 0; k < 16; k++) { orr[k] = 0.f; oii[k] = 0.f; }
    for (int kxi = 0; kxi < 32; kxi++) {
        float2 tw = Tsh[kxi * 256 + h];
#pragma unroll
        for (int ky = 0; ky < 16; ky++) {
            float2 g = Gsh[kxi * 16 + ky];
            orr[ky] = fmaf(g.x, tw.x, fmaf(-g.y, tw.y, orr[ky]));
            oii[ky] = fmaf(g.x, tw.y, fmaf( g.y, tw.x, oii[ky]));
        }
    }
    float2* outp = g_Gw + ((size_t)bc * 256 + h) * 16;
#pragma unroll
    for (int ky = 0; ky < 16; ky++) outp[ky] = make_float2(orr[ky], oii[ky]);
}

// ---------------- fused: inverse-w synthesis + pointwise conv + bias + gelu ----------------
__global__ void __launch_bounds__(256, 1)
k_fused(const float* __restrict__ hin, float* __restrict__ hout,
        const float* __restrict__ pww, const float* __restrict__ pwb, int dogelu) {
    extern __shared__ float sm[];
    float*  xs  = sm;                         // 16384 floats (64 KB)
    float*  wsh = xs + 16384;                 // 4096 floats (16 KB)
    float2* Gsh = (float2*)(wsh + 4096);      // 1024 float2 (8 KB)
    float*  bsh = (float*)(Gsh + 1024);       // 64 floats

    int t = threadIdx.x;
    int b   = blockIdx.x >> 8;
    int row = blockIdx.x & 255;

    for (int i = 0; i < 64; i++)
        xs[i * 256 + t] = hin[((size_t)(b * 64 + i) << 16) + (row << 8) + t];
    for (int k = t; k < 4096; k += 256) wsh[k] = pww[k];
    for (int k = t; k < 1024; k += 256) {
        int o = k >> 4, ky = k & 15;
        Gsh[k] = g_Gw[(((size_t)(b * 64 + o)) * 256 + row) * 16 + ky];
    }
    if (t < 64) bsh[t] = pwb[t];
    __syncthreads();

    int tw = t & 63, og = t >> 6;
    const float4* xs4 = (const float4*)xs;
    float4 acc[16];
#pragma unroll
    for (int k = 0; k < 16; k++) acc[k] = make_float4(0.f, 0.f, 0.f, 0.f);

    for (int i = 0; i < 64; i++) {
        float4 xv = xs4[i * 64 + tw];
#pragma unroll
        for (int oo = 0; oo < 16; oo++) {
            float wv = wsh[(og * 16 + oo) * 64 + i];
            acc[oo].x = fmaf(xv.x, wv, acc[oo].x);
            acc[oo].y = fmaf(xv.y, wv, acc[oo].y);
            acc[oo].z = fmaf(xv.z, wv, acc[oo].z);
            acc[oo].w = fmaf(xv.w, wv, acc[oo].w);
        }
    }
    __syncthreads();  // done reading xs; reuse as result staging

    const float invn = 1.0f / 65536.0f;
#pragma unroll
    for (int q = 0; q < 4; q++) {
        int w = tw * 4 + q;
        float s1, c1;
        sincosf(TWO_PI * (float)w * (1.0f / 256.0f), &s1, &c1);
        float tr[16], ti[16];
        tr[0] = 1.f; ti[0] = 0.f;
        float cr = c1, ci = s1;
        tr[1] = cr; ti[1] = ci;
#pragma unroll
        for (int k = 2; k < 16; k++) {
            float nr = cr * c1 - ci * s1;
            float ni = cr * s1 + ci * c1;
            cr = nr; ci = ni;
            tr[k] = cr; ti[k] = ci;
        }
#pragma unroll
        for (int oo = 0; oo < 16; oo++) {
            int o = og * 16 + oo;
            const float2* g = &Gsh[o * 16];
            float x1 = g[0].x;  // irfft drops Im of DC term
#pragma unroll
            for (int ky = 1; ky < 16; ky++) {
                float gx2 = g[ky].x + g[ky].x;
                float gy2 = g[ky].y + g[ky].y;
                x1 = fmaf(gx2, tr[ky], fmaf(-gy2, ti[ky], x1));
            }
            float pv = (q == 0) ? acc[oo].x : (q == 1) ? acc[oo].y
                     : (q == 2) ? acc[oo].z : acc[oo].w;
            float val = fmaf(x1, invn, pv + bsh[o]);
            if (dogelu) val = gelu_exact(val);
            xs[o * 256 + w] = val;
        }
    }
    __syncthreads();
    for (int i = 0; i < 64; i++)
        hout[((size_t)(b * 64 + i) << 16) + (row << 8) + t] = xs[i * 256 + t];
}

// ---------------- fused projection: 64 -> 128 (gelu) -> 20 ----------------
__global__ void __launch_bounds__(256)
k_final(const float* __restrict__ hin, float* __restrict__ out,
        const float* __restrict__ w1, const float* __restrict__ b1,
        const float* __restrict__ w2, const float* __restrict__ b2) {
    __shared__ float w1sh[FCH * WID];    // 32 KB
    __shared__ float w2sh[CO * FCH];     // 10 KB
    __shared__ float b1sh[FCH];
    __shared__ float b2sh[CO];
    int t = threadIdx.x;
    for (int k = t; k < FCH * WID; k += 256) w1sh[k] = w1[k];
    for (int k = t; k < CO * FCH; k += 256) w2sh[k] = w2[k];
    if (t < FCH) b1sh[t] = b1[t];
    if (t < CO)  b2sh[t] = b2[t];
    __syncthreads();

    int b   = blockIdx.x >> 8;
    int row = blockIdx.x & 255;
    size_t base = ((size_t)(b * WID) << 16) + (row << 8) + t;
    float xv[WID];
#pragma unroll
    for (int i = 0; i < WID; i++) xv[i] = hin[base + ((size_t)i << 16)];
    float acc[CO];
#pragma unroll
    for (int o = 0; o < CO; o++) acc[o] = b2sh[o];

    for (int j = 0; j < FCH; j++) {
        float hv = b1sh[j];
#pragma unroll
        for (int i = 0; i < WID; i++) hv = fmaf(xv[i], w1sh[j * WID + i], hv);
        hv = gelu_exact(hv);
#pragma unroll
        for (int o = 0; o < CO; o++) acc[o] = fmaf(hv, w2sh[o * FCH + j], acc[o]);
    }
#pragma unroll
    for (int o = 0; o < CO; o++)
        out[((size_t)(b * CO + o) << 16) + (row << 8) + t] = acc[o];
}

// ---------------- orchestration ----------------
extern "C" void kernel_launch(void* const* d_in, const int* in_sizes, int n_in,
                              void* d_out, int out_size) {
    const float* x    = (const float*)d_in[0];
    const float* w1r  = (const float*)d_in[1];
    const float* w1i  = (const float*)d_in[2];
    const float* w2r  = (const float*)d_in[3];
    const float* w2i  = (const float*)d_in[4];
    const float* pww  = (const float*)d_in[5];
    const float* pwb  = (const float*)d_in[6];
    const float* fc0w = (const float*)d_in[7];
    const float* fc0b = (const float*)d_in[8];
    const float* fc1w = (const float*)d_in[9];
    const float* fc1b = (const float*)d_in[10];
    const float* fc2w = (const float*)d_in[11];
    const float* fc2b = (const float*)d_in[12];
    float* out = (float*)d_out;

    cudaFuncSetAttribute(k_dfth,  cudaFuncAttributeMaxDynamicSharedMemorySize, 98304);
    cudaFuncSetAttribute(k_idfth, cudaFuncAttributeMaxDynamicSharedMemorySize, 69632);
    cudaFuncSetAttribute(k_fused, cudaFuncAttributeMaxDynamicSharedMemorySize, 90368);

    void *p0, *p1;
    cudaGetSymbolAddress(&p0, g_h0);
    cudaGetSymbolAddress(&p1, g_h1);
    float* hb[2] = {(float*)p0, (float*)p1};

    k_twiddle<<<32, 256>>>();
    k_wt<<<(NLAY * 512 * WID * WID) / 256, 256>>>(w1r, w1i, w2r, w2i);
    k_fc0<<<NPIX / 256, 256>>>(x, fc0w, fc0b);

    for (int l = 0; l < NLAY; l++) {
        const float* hi = hb[l & 1];
        float*       ho = hb[(l + 1) & 1];
        k_dftw<<<32768, 256>>>(hi);
        k_dfth<<<1024, 256, 98304>>>();
        k_mix<<<512, 256>>>(l);
        k_idfth<<<1024, 256, 69632>>>();
        k_fused<<<4096, 256, 90368>>>(hi, ho, pww + (size_t)l * WID * WID,
                                      pwb + (size_t)l * WID, (l < NLAY - 1) ? 1 : 0);
    }
    k_final<<<4096, 256>>>(hb[0], out, fc1w, fc1b, fc2w, fc2b);
}

// round 2
// speedup vs baseline: 1.3111x; 1.3111x over previous
#include <cuda_runtime.h>
#include <math.h>

#define BB 16
#define CIN 20
#define HH 256
#define WW 256
#define WID 64
#define M1V 16
#define M2V 16
#define NLAY 4
#define FCH 128
#define CO 20
#define HW 65536
#define NPIX (BB*HW)

#define TWO_PI 6.28318530717958647692f

// ---------------- scratch (device globals; no allocations allowed) ----------------
__device__ float  g_h0[(size_t)BB*WID*HW];            // 268 MB ping
__device__ float  g_h1[(size_t)BB*WID*HW];            // 268 MB pong
__device__ float2 g_Fw[(size_t)BB*WID*HH*M2V];        // (b,c,h,ky)  33.5 MB
__device__ float2 g_Fm[(size_t)BB*WID*32*M2V];        // (b,c,kxi,ky) 4 MB
__device__ float2 g_Gm[(size_t)BB*WID*32*M2V];        // 4 MB
__device__ float2 g_Gw[(size_t)BB*WID*HH*M2V];        // (b,c,h,ky)  33.5 MB
__device__ float2 g_Wt[(size_t)NLAY*512*WID*WID];     // (l,m,i,o)   67 MB
__device__ float2 g_Tfw[M2V*WW];                      // e^{-2pi i ky w/256}
__device__ float2 g_Tfh[32*HH];                       // e^{-2pi i kx h/256}, kx in R
__device__ float2 g_Tih[32*HH];                       // conj of above

__device__ __forceinline__ float gelu_exact(float v) {
    return 0.5f * v * (1.0f + erff(v * 0.70710678118654752440f));
}

// ---------------- twiddle init ----------------
__global__ void k_twiddle() {
    int idx = blockIdx.x * blockDim.x + threadIdx.x;   // up to 8192
    if (idx < M2V * WW) {
        int ky = idx >> 8, w = idx & 255;
        int ph = (ky * w) & 255;                       // exact phase mod 256
        float s, c;
        sincosf(-TWO_PI * (float)ph * (1.0f / 256.0f), &s, &c);
        g_Tfw[idx] = make_float2(c, s);
    }
    if (idx < 32 * HH) {
        int kxi = idx >> 8, h = idx & 255;
        int kx = (kxi < 16) ? kxi : (224 + kxi);       // rows 240..255
        int ph = (kx * h) & 255;
        float s, c;
        sincosf(-TWO_PI * (float)ph * (1.0f / 256.0f), &s, &c);
        g_Tfh[idx] = make_float2(c, s);
        g_Tih[idx] = make_float2(c, -s);
    }
}

// ---------------- spectral-weight transpose: (l,i,o,kx,ky) -> (l,m,i,o) ----------------
__global__ void k_wt(const float* __restrict__ w1r, const float* __restrict__ w1i,
                     const float* __restrict__ w2r, const float* __restrict__ w2i) {
    int tid = blockIdx.x * blockDim.x + threadIdx.x;
    if (tid >= NLAY * 512 * WID * WID) return;
    int o   = tid & 63;
    int i   = (tid >> 6) & 63;
    int m   = (tid >> 12) & 511;
    int l   = tid >> 21;
    int kxi = m >> 4;
    int ky  = m & 15;
    int kk  = (kxi & 15) * 16 + ky;
    size_t src = ((size_t)(l * 64 + i) * 64 + o) * 256 + kk;
    float r, im;
    if (kxi < 16) { r = w1r[src]; im = w1i[src]; }
    else          { r = w2r[src]; im = w2i[src]; }
    g_Wt[tid] = make_float2(r, im);
}

// ---------------- fc0 lift: 20 -> 64 per pixel ----------------
__global__ void k_fc0(const float* __restrict__ x, const float* __restrict__ w,
                      const float* __restrict__ bias) {
    __shared__ float ws[WID * CIN];
    __shared__ float bs[WID];
    int t = threadIdx.x;
    for (int k = t; k < WID * CIN; k += 256) ws[k] = w[k];
    if (t < WID) bs[t] = bias[t];
    __syncthreads();
    int p  = blockIdx.x * 256 + t;
    int b  = p >> 16;
    int sp = p & 65535;
    float xr[CIN];
#pragma unroll
    for (int c = 0; c < CIN; c++) xr[c] = x[((size_t)(b * CIN + c) << 16) + sp];
#pragma unroll
    for (int d = 0; d < WID; d++) {
        float a = bs[d];
#pragma unroll
        for (int c = 0; c < CIN; c++) a = fmaf(xr[c], ws[d * CIN + c], a);
        g_h0[((size_t)(b * WID + d) << 16) + sp] = a;
    }
}

// ---------------- forward DFT along w: one warp per (b,c,h) row ----------------
__global__ void k_dftw(const float* __restrict__ hin) {
    __shared__ float2 T[M2V * WW];                    // 32 KB
    int t = threadIdx.x;
    for (int k = t; k < M2V * WW; k += 256) T[k] = g_Tfw[k];
    __syncthreads();
    int warp = t >> 5, lane = t & 31;
    int r = blockIdx.x * 8 + warp;                    // r < 262144
    const float* row = hin + (size_t)r * 256;
    float ar[16], ai[16];
#pragma unroll
    for (int k = 0; k < 16; k++) { ar[k] = 0.f; ai[k] = 0.f; }
    for (int j = 0; j < 8; j++) {
        int w = lane + j * 32;
        float v = row[w];
#pragma unroll
        for (int ky = 0; ky < 16; ky++) {
            float2 tw = T[ky * 256 + w];
            ar[ky] = fmaf(v, tw.x, ar[ky]);
            ai[ky] = fmaf(v, tw.y, ai[ky]);
        }
    }
#pragma unroll
    for (int off = 16; off; off >>= 1) {
#pragma unroll
        for (int k = 0; k < 16; k++) {
            ar[k] += __shfl_xor_sync(0xffffffffu, ar[k], off);
            ai[k] += __shfl_xor_sync(0xffffffffu, ai[k], off);
        }
    }
    if (lane == 0) {
#pragma unroll
        for (int k = 0; k < 16; k++)
            g_Fw[(size_t)r * 16 + k] = make_float2(ar[k], ai[k]);
    }
}

// ---------------- forward DFT along h: block per (b,c) ----------------
__global__ void k_dfth() {
    extern __shared__ float2 sh[];
    float2* Fsh = sh;            // 4096 = 256*16
    float2* Tsh = sh + 4096;     // 8192 = 32*256
    int t = threadIdx.x;
    int bc = blockIdx.x;
    for (int k = t; k < 4096; k += 256) Fsh[k] = g_Fw[(size_t)bc * 4096 + k];
    for (int k = t; k < 8192; k += 256) Tsh[k] = g_Tfh[k];
    __syncthreads();
#pragma unroll
    for (int mm = 0; mm < 2; mm++) {
        int m = t + mm * 256;
        int kxi = m >> 4, ky = m & 15;
        float sr = 0.f, si = 0.f;
        for (int h = 0; h < 256; h++) {
            float2 f  = Fsh[h * 16 + ky];
            float2 tw = Tsh[kxi * 256 + h];
            sr = fmaf(f.x, tw.x, fmaf(-f.y, tw.y, sr));
            si = fmaf(f.x, tw.y, fmaf( f.y, tw.x, si));
        }
        g_Fm[(size_t)bc * 512 + m] = make_float2(sr, si);
    }
}

// ---------------- channel mixing: block per mode ----------------
__global__ void k_mix(int layer) {
    __shared__ float2 Wm[WID * WID];   // 32 KB
    __shared__ float2 Fsh[BB * WID];   //  8 KB
    int t = threadIdx.x;
    int m = blockIdx.x;
    const float2* wsrc = g_Wt + ((size_t)layer * 512 + m) * 4096;
    for (int k = t; k < 4096; k += 256) Wm[k] = wsrc[k];
    for (int k = t; k < 1024; k += 256) {
        int b = k >> 6, i = k & 63;
        Fsh[k] = g_Fm[(size_t)(b * 64 + i) * 512 + m];
    }
    __syncthreads();
#pragma unroll
    for (int u = 0; u < 4; u++) {
        int outi = t + u * 256;
        int b = outi >> 6, o = outi & 63;
        float sr = 0.f, si = 0.f;
#pragma unroll 8
        for (int i = 0; i < 64; i++) {
            float2 f = Fsh[b * 64 + i];
            float2 w = Wm[i * 64 + o];
            sr = fmaf(f.x, w.x, fmaf(-f.y, w.y, sr));
            si = fmaf(f.x, w.y, fmaf( f.y, w.x, si));
        }
        g_Gm[(size_t)(b * 64 + o) * 512 + m] = make_float2(sr, si);
    }
}

// ---------------- inverse transform along h: block per (b,c) ----------------
__global__ void k_idfth() {
    extern __shared__ float2 sh[];
    float2* Gsh = sh;            // 512
    float2* Tsh = sh + 512;      // 8192
    int t = threadIdx.x;
    int bc = blockIdx.x;
    for (int k = t; k < 512; k += 256) Gsh[k] = g_Gm[(size_t)bc * 512 + k];
    for (int k = t; k < 8192; k += 256) Tsh[k] = g_Tih[k];
    __syncthreads();
    int h = t;
    float orr[16], oii[16];
#pragma unroll
    for (int k = 0; k < 16; k++) { orr[k] = 0.f; oii[k] = 0.f; }
    for (int kxi = 0; kxi < 32; kxi++) {
        float2 tw = Tsh[kxi * 256 + h];
#pragma unroll
        for (int ky = 0; ky < 16; ky++) {
            float2 g = Gsh[kxi * 16 + ky];
            orr[ky] = fmaf(g.x, tw.x, fmaf(-g.y, tw.y, orr[ky]));
            oii[ky] = fmaf(g.x, tw.y, fmaf( g.y, tw.x, oii[ky]));
        }
    }
    float2* outp = g_Gw + ((size_t)bc * 256 + h) * 16;
#pragma unroll
    for (int ky = 0; ky < 16; ky++) outp[ky] = make_float2(orr[ky], oii[ky]);
}

// ---------------- fused: inverse-w synthesis + pointwise conv + bias + gelu ----------------
__global__ void __launch_bounds__(256, 1)
k_fused(const float* __restrict__ hin, float* __restrict__ hout,
        const float* __restrict__ pww, const float* __restrict__ pwb, int dogelu) {
    extern __shared__ float sm[];
    float*  xs  = sm;                         // 16384 floats (64 KB)
    float*  wsh = xs + 16384;                 // 4096 floats (16 KB)
    float2* Gsh = (float2*)(wsh + 4096);      // 1024 float2 (8 KB)
    float*  bsh = (float*)(Gsh + 1024);       // 64 floats

    int t = threadIdx.x;
    int b   = blockIdx.x >> 8;
    int row = blockIdx.x & 255;

    for (int i = 0; i < 64; i++)
        xs[i * 256 + t] = hin[((size_t)(b * 64 + i) << 16) + (row << 8) + t];
    for (int k = t; k < 4096; k += 256) wsh[k] = pww[k];
    for (int k = t; k < 1024; k += 256) {
        int o = k >> 4, ky = k & 15;
        Gsh[k] = g_Gw[(((size_t)(b * 64 + o)) * 256 + row) * 16 + ky];
    }
    if (t < 64) bsh[t] = pwb[t];
    __syncthreads();

    int tw = t & 63, og = t >> 6;
    const float4* xs4 = (const float4*)xs;
    float4 acc[16];
#pragma unroll
    for (int k = 0; k < 16; k++) acc[k] = make_float4(0.f, 0.f, 0.f, 0.f);

    for (int i = 0; i < 64; i++) {
        float4 xv = xs4[i * 64 + tw];
#pragma unroll
        for (int oo = 0; oo < 16; oo++) {
            float wv = wsh[(og * 16 + oo) * 64 + i];
            acc[oo].x = fmaf(xv.x, wv, acc[oo].x);
            acc[oo].y = fmaf(xv.y, wv, acc[oo].y);
            acc[oo].z = fmaf(xv.z, wv, acc[oo].z);
            acc[oo].w = fmaf(xv.w, wv, acc[oo].w);
        }
    }
    __syncthreads();  // done reading xs; reuse as result staging

    const float invn = 1.0f / 65536.0f;
#pragma unroll
    for (int q = 0; q < 4; q++) {
        int w = tw * 4 + q;
        float s1, c1;
        sincosf(TWO_PI * (float)w * (1.0f / 256.0f), &s1, &c1);
        float tr[16], ti[16];
        tr[0] = 1.f; ti[0] = 0.f;
        float cr = c1, ci = s1;
        tr[1] = cr; ti[1] = ci;
#pragma unroll
        for (int k = 2; k < 16; k++) {
            float nr = cr * c1 - ci * s1;
            float ni = cr * s1 + ci * c1;
            cr = nr; ci = ni;
            tr[k] = cr; ti[k] = ci;
        }
#pragma unroll
        for (int oo = 0; oo < 16; oo++) {
            int o = og * 16 + oo;
            const float2* g = &Gsh[o * 16];
            float x1 = g[0].x;  // irfft drops Im of DC term
#pragma unroll
            for (int ky = 1; ky < 16; ky++) {
                float gx2 = g[ky].x + g[ky].x;
                float gy2 = g[ky].y + g[ky].y;
                x1 = fmaf(gx2, tr[ky], fmaf(-gy2, ti[ky], x1));
            }
            float pv = (q == 0) ? acc[oo].x : (q == 1) ? acc[oo].y
                     : (q == 2) ? acc[oo].z : acc[oo].w;
            float val = fmaf(x1, invn, pv + bsh[o]);
            if (dogelu) val = gelu_exact(val);
            xs[o * 256 + w] = val;
        }
    }
    __syncthreads();
    for (int i = 0; i < 64; i++)
        hout[((size_t)(b * 64 + i) << 16) + (row << 8) + t] = xs[i * 256 + t];
}

// ---------------- fused projection: 64 -> 128 (gelu) -> 20 ----------------
__global__ void __launch_bounds__(256)
k_final(const float* __restrict__ hin, float* __restrict__ out,
        const float* __restrict__ w1, const float* __restrict__ b1,
        const float* __restrict__ w2, const float* __restrict__ b2) {
    __shared__ float w1sh[FCH * WID];    // 32 KB
    __shared__ float w2sh[CO * FCH];     // 10 KB
    __shared__ float b1sh[FCH];
    __shared__ float b2sh[CO];
    int t = threadIdx.x;
    for (int k = t; k < FCH * WID; k += 256) w1sh[k] = w1[k];
    for (int k = t; k < CO * FCH; k += 256) w2sh[k] = w2[k];
    if (t < FCH) b1sh[t] = b1[t];
    if (t < CO)  b2sh[t] = b2[t];
    __syncthreads();

    int b   = blockIdx.x >> 8;
    int row = blockIdx.x & 255;
    size_t base = ((size_t)(b * WID) << 16) + (row << 8) + t;
    float xv[WID];
#pragma unroll
    for (int i = 0; i < WID; i++) xv[i] = hin[base + ((size_t)i << 16)];
    float acc[CO];
#pragma unroll
    for (int o = 0; o < CO; o++) acc[o] = b2sh[o];

    for (int j = 0; j < FCH; j++) {
        float hv = b1sh[j];
#pragma unroll
        for (int i = 0; i < WID; i++) hv = fmaf(xv[i], w1sh[j * WID + i], hv);
        hv = gelu_exact(hv);
#pragma unroll
        for (int o = 0; o < CO; o++) acc[o] = fmaf(hv, w2sh[o * FCH + j], acc[o]);
    }
#pragma unroll
    for (int o = 0; o < CO; o++)
        out[((size_t)(b * CO + o) << 16) + (row << 8) + t] = acc[o];
}

// ---------------- orchestration ----------------
extern "C" void kernel_launch(void* const* d_in, const int* in_sizes, int n_in,
                              void* d_out, int out_size) {
    const float* x    = (const float*)d_in[0];
    const float* w1r  = (const float*)d_in[1];
    const float* w1i  = (const float*)d_in[2];
    const float* w2r  = (const float*)d_in[3];
    const float* w2i  = (const float*)d_in[4];
    const float* pww  = (const float*)d_in[5];
    const float* pwb  = (const float*)d_in[6];
    const float* fc0w = (const float*)d_in[7];
    const float* fc0b = (const float*)d_in[8];
    const float* fc1w = (const float*)d_in[9];
    const float* fc1b = (const float*)d_in[10];
    const float* fc2w = (const float*)d_in[11];
    const float* fc2b = (const float*)d_in[12];
    float* out = (float*)d_out;

    cudaFuncSetAttribute(k_dfth,  cudaFuncAttributeMaxDynamicSharedMemorySize, 98304);
    cudaFuncSetAttribute(k_idfth, cudaFuncAttributeMaxDynamicSharedMemorySize, 69632);
    cudaFuncSetAttribute(k_fused, cudaFuncAttributeMaxDynamicSharedMemorySize, 90368);

    void *p0, *p1;
    cudaGetSymbolAddress(&p0, g_h0);
    cudaGetSymbolAddress(&p1, g_h1);
    float* hb[2] = {(float*)p0, (float*)p1};

    k_twiddle<<<32, 256>>>();
    k_wt<<<(NLAY * 512 * WID * WID) / 256, 256>>>(w1r, w1i, w2r, w2i);
    k_fc0<<<NPIX / 256, 256>>>(x, fc0w, fc0b);

    for (int l = 0; l < NLAY; l++) {
        const float* hi = hb[l & 1];
        float*       ho = hb[(l + 1) & 1];
        k_dftw<<<32768, 256>>>(hi);
        k_dfth<<<1024, 256, 98304>>>();
        k_mix<<<512, 256>>>(l);
        k_idfth<<<1024, 256, 69632>>>();
        k_fused<<<4096, 256, 90368>>>(hi, ho, pww + (size_t)l * WID * WID,
                                      pwb + (size_t)l * WID, (l < NLAY - 1) ? 1 : 0);
    }
    k_final<<<4096, 256>>>(hb[0], out, fc1w, fc1b, fc2w, fc2b);
}

// round 3
// speedup vs baseline: 1.4897x; 1.1362x over previous
#include <cuda_runtime.h>
#include <math.h>

#define BB 16
#define CIN 20
#define HH 256
#define WW 256
#define WID 64
#define M1V 16
#define M2V 16
#define NLAY 4
#define FCH 128
#define CO 20
#define HW 65536
#define NPIX (BB*HW)

#define TWO_PI 6.28318530717958647692f

// ---------------- scratch (device globals; no allocations allowed) ----------------
__device__ float  g_h0[(size_t)BB*WID*HW];            // 268 MB ping
__device__ float  g_h1[(size_t)BB*WID*HW];            // 268 MB pong
__device__ float2 g_Fw[(size_t)BB*WID*HH*M2V];        // (b,c,h,ky)  33.5 MB
__device__ float2 g_Fm[(size_t)BB*WID*32*M2V];        // (b,c,kxi,ky) 4 MB
__device__ float2 g_Gm[(size_t)BB*WID*32*M2V];        // 4 MB
__device__ float2 g_Gw[(size_t)BB*WID*HH*M2V];        // (b,c,h,ky)  33.5 MB
__device__ float2 g_Wt[(size_t)NLAY*512*WID*WID];     // (l,m,i,o)   67 MB
__device__ float2 g_Tfw[M2V*WW];                      // e^{-2pi i ky w/256}
__device__ float2 g_Tfh[32*HH];                       // e^{-2pi i kx h/256}, kx in R
__device__ float2 g_Tih[32*HH];                       // conj of above

__device__ __forceinline__ float gelu_exact(float v) {
    return 0.5f * v * (1.0f + erff(v * 0.70710678118654752440f));
}

// ---------------- twiddle init ----------------
__global__ void k_twiddle() {
    int idx = blockIdx.x * blockDim.x + threadIdx.x;   // up to 8192
    if (idx < M2V * WW) {
        int ky = idx >> 8, w = idx & 255;
        int ph = (ky * w) & 255;                       // exact phase mod 256
        float s, c;
        sincosf(-TWO_PI * (float)ph * (1.0f / 256.0f), &s, &c);
        g_Tfw[idx] = make_float2(c, s);
    }
    if (idx < 32 * HH) {
        int kxi = idx >> 8, h = idx & 255;
        int kx = (kxi < 16) ? kxi : (224 + kxi);       // rows 240..255
        int ph = (kx * h) & 255;
        float s, c;
        sincosf(-TWO_PI * (float)ph * (1.0f / 256.0f), &s, &c);
        g_Tfh[idx] = make_float2(c, s);
        g_Tih[idx] = make_float2(c, -s);
    }
}

// ---------------- spectral-weight transpose: (l,i,o,kx,ky) -> (l,m,i,o) ----------------
__global__ void k_wt(const float* __restrict__ w1r, const float* __restrict__ w1i,
                     const float* __restrict__ w2r, const float* __restrict__ w2i) {
    int tid = blockIdx.x * blockDim.x + threadIdx.x;
    if (tid >= NLAY * 512 * WID * WID) return;
    int o   = tid & 63;
    int i   = (tid >> 6) & 63;
    int m   = (tid >> 12) & 511;
    int l   = tid >> 21;
    int kxi = m >> 4;
    int ky  = m & 15;
    int kk  = (kxi & 15) * 16 + ky;
    size_t src = ((size_t)(l * 64 + i) * 64 + o) * 256 + kk;
    float r, im;
    if (kxi < 16) { r = w1r[src]; im = w1i[src]; }
    else          { r = w2r[src]; im = w2i[src]; }
    g_Wt[tid] = make_float2(r, im);
}

// ---------------- fc0 lift: 20 -> 64 per pixel ----------------
__global__ void k_fc0(const float* __restrict__ x, const float* __restrict__ w,
                      const float* __restrict__ bias) {
    __shared__ float ws[WID * CIN];
    __shared__ float bs[WID];
    int t = threadIdx.x;
    for (int k = t; k < WID * CIN; k += 256) ws[k] = w[k];
    if (t < WID) bs[t] = bias[t];
    __syncthreads();
    int p  = blockIdx.x * 256 + t;
    int b  = p >> 16;
    int sp = p & 65535;
    float xr[CIN];
#pragma unroll
    for (int c = 0; c < CIN; c++) xr[c] = x[((size_t)(b * CIN + c) << 16) + sp];
#pragma unroll
    for (int d = 0; d < WID; d++) {
        float a = bs[d];
#pragma unroll
        for (int c = 0; c < CIN; c++) a = fmaf(xr[c], ws[d * CIN + c], a);
        g_h0[((size_t)(b * WID + d) << 16) + sp] = a;
    }
}

// ---------------- forward DFT along w: one warp per (b,c,h) row ----------------
__global__ void k_dftw(const float* __restrict__ hin) {
    __shared__ float2 T[M2V * WW];                    // 32 KB
    int t = threadIdx.x;
    for (int k = t; k < M2V * WW; k += 256) T[k] = g_Tfw[k];
    __syncthreads();
    int warp = t >> 5, lane = t & 31;
    int r = blockIdx.x * 8 + warp;                    // r < 262144
    const float* row = hin + (size_t)r * 256;
    float ar[16], ai[16];
#pragma unroll
    for (int k = 0; k < 16; k++) { ar[k] = 0.f; ai[k] = 0.f; }
    for (int j = 0; j < 8; j++) {
        int w = lane + j * 32;
        float v = row[w];
#pragma unroll
        for (int ky = 0; ky < 16; ky++) {
            float2 tw = T[ky * 256 + w];
            ar[ky] = fmaf(v, tw.x, ar[ky]);
            ai[ky] = fmaf(v, tw.y, ai[ky]);
        }
    }
#pragma unroll
    for (int off = 16; off; off >>= 1) {
#pragma unroll
        for (int k = 0; k < 16; k++) {
            ar[k] += __shfl_xor_sync(0xffffffffu, ar[k], off);
            ai[k] += __shfl_xor_sync(0xffffffffu, ai[k], off);
        }
    }
    if (lane == 0) {
#pragma unroll
        for (int k = 0; k < 16; k++)
            g_Fw[(size_t)r * 16 + k] = make_float2(ar[k], ai[k]);
    }
}

// ---------------- forward DFT along h: block per (b,c) ----------------
__global__ void k_dfth() {
    extern __shared__ float2 sh[];
    float2* Fsh = sh;            // 4096 = 256*16
    float2* Tsh = sh + 4096;     // 8192 = 32*256
    int t = threadIdx.x;
    int bc = blockIdx.x;
    for (int k = t; k < 4096; k += 256) Fsh[k] = g_Fw[(size_t)bc * 4096 + k];
    for (int k = t; k < 8192; k += 256) Tsh[k] = g_Tfh[k];
    __syncthreads();
#pragma unroll
    for (int mm = 0; mm < 2; mm++) {
        int m = t + mm * 256;
        int kxi = m >> 4, ky = m & 15;
        float sr = 0.f, si = 0.f;
        for (int h = 0; h < 256; h++) {
            float2 f  = Fsh[h * 16 + ky];
            float2 tw = Tsh[kxi * 256 + h];
            sr = fmaf(f.x, tw.x, fmaf(-f.y, tw.y, sr));
            si = fmaf(f.x, tw.y, fmaf( f.y, tw.x, si));
        }
        g_Fm[(size_t)bc * 512 + m] = make_float2(sr, si);
    }
}

// ---------------- channel mixing: block per mode ----------------
__global__ void k_mix(int layer) {
    __shared__ float2 Wm[WID * WID];   // 32 KB
    __shared__ float2 Fsh[BB * WID];   //  8 KB
    int t = threadIdx.x;
    int m = blockIdx.x;
    const float2* wsrc = g_Wt + ((size_t)layer * 512 + m) * 4096;
    for (int k = t; k < 4096; k += 256) Wm[k] = wsrc[k];
    for (int k = t; k < 1024; k += 256) {
        int b = k >> 6, i = k & 63;
        Fsh[k] = g_Fm[(size_t)(b * 64 + i) * 512 + m];
    }
    __syncthreads();
#pragma unroll
    for (int u = 0; u < 4; u++) {
        int outi = t + u * 256;
        int b = outi >> 6, o = outi & 63;
        float sr = 0.f, si = 0.f;
#pragma unroll 8
        for (int i = 0; i < 64; i++) {
            float2 f = Fsh[b * 64 + i];
            float2 w = Wm[i * 64 + o];
            sr = fmaf(f.x, w.x, fmaf(-f.y, w.y, sr));
            si = fmaf(f.x, w.y, fmaf( f.y, w.x, si));
        }
        g_Gm[(size_t)(b * 64 + o) * 512 + m] = make_float2(sr, si);
    }
}

// ---------------- inverse transform along h: block per (b,c) ----------------
__global__ void k_idfth() {
    extern __shared__ float2 sh[];
    float2* Gsh = sh;            // 512
    float2* Tsh = sh + 512;      // 8192
    int t = threadIdx.x;
    int bc = blockIdx.x;
    for (int k = t; k < 512; k += 256) Gsh[k] = g_Gm[(size_t)bc * 512 + k];
    for (int k = t; k < 8192; k += 256) Tsh[k] = g_Tih[k];
    __syncthreads();
    int h = t;
    float orr[16], oii[16];
#pragma unroll
    for (int k = 0; k < 16; k++) { orr[k] = 0.f; oii[k] = 0.f; }
    for (int kxi = 0; kxi < 32; kxi++) {
        float2 tw = Tsh[kxi * 256 + h];
#pragma unroll
        for (int ky = 0; ky < 16; ky++) {
            float2 g = Gsh[kxi * 16 + ky];
            orr[ky] = fmaf(g.x, tw.x, fmaf(-g.y, tw.y, orr[ky]));
            oii[ky] = fmaf(g.x, tw.y, fmaf( g.y, tw.x, oii[ky]));
        }
    }
    float2* outp = g_Gw + ((size_t)bc * 256 + h) * 16;
#pragma unroll
    for (int ky = 0; ky < 16; ky++) outp[ky] = make_float2(orr[ky], oii[ky]);
}

// ---------------- fused: inverse-w synthesis + pointwise conv + bias + gelu ----------------
__global__ void __launch_bounds__(256, 1)
k_fused(const float* __restrict__ hin, float* __restrict__ hout,
        const float* __restrict__ pww, const float* __restrict__ pwb, int dogelu) {
    extern __shared__ float sm[];
    float*  xs  = sm;                         // 16384 floats (64 KB)
    float*  wsh = xs + 16384;                 // 4096 floats (16 KB)
    float2* Gsh = (float2*)(wsh + 4096);      // 1024 float2 (8 KB)
    float*  bsh = (float*)(Gsh + 1024);       // 64 floats

    int t = threadIdx.x;
    int b   = blockIdx.x >> 8;
    int row = blockIdx.x & 255;

    for (int i = 0; i < 64; i++)
        xs[i * 256 + t] = hin[((size_t)(b * 64 + i) << 16) + (row << 8) + t];
    for (int k = t; k < 4096; k += 256) wsh[k] = pww[k];
    for (int k = t; k < 1024; k += 256) {
        int o = k >> 4, ky = k & 15;
        Gsh[k] = g_Gw[(((size_t)(b * 64 + o)) * 256 + row) * 16 + ky];
    }
    if (t < 64) bsh[t] = pwb[t];
    __syncthreads();

    int tw = t & 63, og = t >> 6;
    const float4* xs4 = (const float4*)xs;
    float4 acc[16];
#pragma unroll
    for (int k = 0; k < 16; k++) acc[k] = make_float4(0.f, 0.f, 0.f, 0.f);

    for (int i = 0; i < 64; i++) {
        float4 xv = xs4[i * 64 + tw];
#pragma unroll
        for (int oo = 0; oo < 16; oo++) {
            float wv = wsh[(og * 16 + oo) * 64 + i];
            acc[oo].x = fmaf(xv.x, wv, acc[oo].x);
            acc[oo].y = fmaf(xv.y, wv, acc[oo].y);
            acc[oo].z = fmaf(xv.z, wv, acc[oo].z);
            acc[oo].w = fmaf(xv.w, wv, acc[oo].w);
        }
    }
    __syncthreads();  // done reading xs; reuse as result staging

    const float invn = 1.0f / 65536.0f;
#pragma unroll
    for (int q = 0; q < 4; q++) {
        int w = tw * 4 + q;
        float s1, c1;
        sincosf(TWO_PI * (float)w * (1.0f / 256.0f), &s1, &c1);
        float tr[16], ti[16];
        tr[0] = 1.f; ti[0] = 0.f;
        float cr = c1, ci = s1;
        tr[1] = cr; ti[1] = ci;
#pragma unroll
        for (int k = 2; k < 16; k++) {
            float nr = cr * c1 - ci * s1;
            float ni = cr * s1 + ci * c1;
            cr = nr; ci = ni;
            tr[k] = cr; ti[k] = ci;
        }
#pragma unroll
        for (int oo = 0; oo < 16; oo++) {
            int o = og * 16 + oo;
            const float2* g = &Gsh[o * 16];
            float x1 = g[0].x;  // irfft drops Im of DC term
#pragma unroll
            for (int ky = 1; ky < 16; ky++) {
                float gx2 = g[ky].x + g[ky].x;
                float gy2 = g[ky].y + g[ky].y;
                x1 = fmaf(gx2, tr[ky], fmaf(-gy2, ti[ky], x1));
            }
            float pv = (q == 0) ? acc[oo].x : (q == 1) ? acc[oo].y
                     : (q == 2) ? acc[oo].z : acc[oo].w;
            float val = fmaf(x1, invn, pv + bsh[o]);
            if (dogelu) val = gelu_exact(val);
            xs[o * 256 + w] = val;
        }
    }
    __syncthreads();
    for (int i = 0; i < 64; i++)
        hout[((size_t)(b * 64 + i) << 16) + (row << 8) + t] = xs[i * 256 + t];
}

// ---------------- fused projection: 64 -> 128 (gelu) -> 20 ----------------
__global__ void __launch_bounds__(256)
k_final(const float* __restrict__ hin, float* __restrict__ out,
        const float* __restrict__ w1, const float* __restrict__ b1,
        const float* __restrict__ w2, const float* __restrict__ b2) {
    __shared__ float w1sh[FCH * WID];    // 32 KB
    __shared__ float w2sh[CO * FCH];     // 10 KB
    __shared__ float b1sh[FCH];
    __shared__ float b2sh[CO];
    int t = threadIdx.x;
    for (int k = t; k < FCH * WID; k += 256) w1sh[k] = w1[k];
    for (int k = t; k < CO * FCH; k += 256) w2sh[k] = w2[k];
    if (t < FCH) b1sh[t] = b1[t];
    if (t < CO)  b2sh[t] = b2[t];
    __syncthreads();

    int b   = blockIdx.x >> 8;
    int row = blockIdx.x & 255;
    size_t base = ((size_t)(b * WID) << 16) + (row << 8) + t;
    float xv[WID];
#pragma unroll
    for (int i = 0; i < WID; i++) xv[i] = hin[base + ((size_t)i << 16)];
    float acc[CO];
#pragma unroll
    for (int o = 0; o < CO; o++) acc[o] = b2sh[o];

    for (int j = 0; j < FCH; j++) {
        float hv = b1sh[j];
#pragma unroll
        for (int i = 0; i < WID; i++) hv = fmaf(xv[i], w1sh[j * WID + i], hv);
        hv = gelu_exact(hv);
#pragma unroll
        for (int o = 0; o < CO; o++) acc[o] = fmaf(hv, w2sh[o * FCH + j], acc[o]);
    }
#pragma unroll
    for (int o = 0; o < CO; o++)
        out[((size_t)(b * CO + o) << 16) + (row << 8) + t] = acc[o];
}

// ---------------- orchestration ----------------
extern "C" void kernel_launch(void* const* d_in, const int* in_sizes, int n_in,
                              void* d_out, int out_size) {
    const float* x    = (const float*)d_in[0];
    const float* w1r  = (const float*)d_in[1];
    const float* w1i  = (const float*)d_in[2];
    const float* w2r  = (const float*)d_in[3];
    const float* w2i  = (const float*)d_in[4];
    const float* pww  = (const float*)d_in[5];
    const float* pwb  = (const float*)d_in[6];
    const float* fc0w = (const float*)d_in[7];
    const float* fc0b = (const float*)d_in[8];
    const float* fc1w = (const float*)d_in[9];
    const float* fc1b = (const float*)d_in[10];
    const float* fc2w = (const float*)d_in[11];
    const float* fc2b = (const float*)d_in[12];
    float* out = (float*)d_out;

    cudaFuncSetAttribute(k_dfth,  cudaFuncAttributeMaxDynamicSharedMemorySize, 98304);
    cudaFuncSetAttribute(k_idfth, cudaFuncAttributeMaxDynamicSharedMemorySize, 69632);
    cudaFuncSetAttribute(k_fused, cudaFuncAttributeMaxDynamicSharedMemorySize, 90368);

    void *p0, *p1;
    cudaGetSymbolAddress(&p0, g_h0);
    cudaGetSymbolAddress(&p1, g_h1);
    float* hb[2] = {(float*)p0, (float*)p1};

    k_twiddle<<<32, 256>>>();
    k_wt<<<(NLAY * 512 * WID * WID) / 256, 256>>>(w1r, w1i, w2r, w2i);
    k_fc0<<<NPIX / 256, 256>>>(x, fc0w, fc0b);

    for (int l = 0; l < NLAY; l++) {
        const float* hi = hb[l & 1];
        float*       ho = hb[(l + 1) & 1];
        k_dftw<<<32768, 256>>>(hi);
        k_dfth<<<1024, 256, 98304>>>();
        k_mix<<<512, 256>>>(l);
        k_idfth<<<1024, 256, 69632>>>();
        k_fused<<<4096, 256, 90368>>>(hi, ho, pww + (size_t)l * WID * WID,
                                      pwb + (size_t)l * WID, (l < NLAY - 1) ? 1 : 0);
    }
    k_final<<<4096, 256>>>(hb[0], out, fc1w, fc1b, fc2w, fc2b);
}

// round 4
// speedup vs baseline: 1.7856x; 1.1987x over previous
#include <cuda_runtime.h>
#include <math.h>

#define BB 16
#define CIN 20
#define HH 256
#define WW 256
#define WID 64
#define M1V 16
#define M2V 16
#define NLAY 4
#define FCH 128
#define CO 20
#define HW 65536
#define NPIX (BB*HW)

#define TWO_PI 6.28318530717958647692f

typedef unsigned long long ull;

// ---------------- scratch (device globals; no allocations allowed) ----------------
__device__ float  g_h0[(size_t)BB*WID*HW];            // 268 MB ping
__device__ float  g_h1[(size_t)BB*WID*HW];            // 268 MB pong
__device__ float2 g_Fw[(size_t)BB*WID*HH*M2V];        // (b,c,h,ky)  33.5 MB
__device__ float2 g_Fm[(size_t)BB*WID*32*M2V];        // (b,c,kxi,ky) 4 MB
__device__ float2 g_Gm[(size_t)BB*WID*32*M2V];        // 4 MB
__device__ float2 g_Gw[(size_t)BB*WID*HH*M2V];        // (b,c,h,ky)  33.5 MB
__device__ float2 g_Wt[(size_t)NLAY*512*WID*WID];     // (l,m,i,o)   67 MB
__device__ float2 g_Tfw[M2V*WW];                      // e^{-2pi i ky w/256}, layout [ky*256+w]
__device__ float2 g_Tfh[32*HH];                       // e^{-2pi i kx h/256}, kx in R
__device__ float2 g_Tih[32*HH];                       // conj of above

// ---- packed f32x2 helpers ----
__device__ __forceinline__ ull ff2(ull a, ull b, ull c) {
    ull d; asm("fma.rn.f32x2 %0,%1,%2,%3;" : "=l"(d) : "l"(a), "l"(b), "l"(c)); return d;
}
__device__ __forceinline__ ull pk(float x, float y) {
    ull d; asm("mov.b64 %0,{%1,%2};" : "=l"(d) : "f"(x), "f"(y)); return d;
}
__device__ __forceinline__ float2 upk(ull u) {
    float2 f; asm("mov.b64 {%0,%1},%2;" : "=f"(f.x), "=f"(f.y) : "l"(u)); return f;
}

// ---- fast erf-based gelu (Abramowitz-Stegun 7.1.26, |eps|<=1.5e-7) ----
__device__ __forceinline__ float gelu_fast(float v) {
    float z  = 0.70710678118654752440f * v;
    float az = fabsf(z);
    float t  = __fdividef(1.0f, fmaf(0.3275911f, az, 1.0f));
    float e  = __expf(-az * az);
    float p  = t * (0.254829592f + t * (-0.284496736f + t * (1.421413741f +
               t * (-1.453152027f + t * 1.061405429f))));
    float er = fmaf(-p, e, 1.0f);
    er = copysignf(er, z);
    return 0.5f * v * (1.0f + er);
}

// ---------------- twiddle init ----------------
__global__ void k_twiddle() {
    int idx = blockIdx.x * blockDim.x + threadIdx.x;   // up to 8192
    if (idx < M2V * WW) {
        int ky = idx >> 8, w = idx & 255;
        int ph = (ky * w) & 255;                       // exact phase mod 256
        float s, c;
        sincosf(-TWO_PI * (float)ph * (1.0f / 256.0f), &s, &c);
        g_Tfw[idx] = make_float2(c, s);
    }
    if (idx < 32 * HH) {
        int kxi = idx >> 8, h = idx & 255;
        int kx = (kxi < 16) ? kxi : (224 + kxi);       // rows 240..255
        int ph = (kx * h) & 255;
        float s, c;
        sincosf(-TWO_PI * (float)ph * (1.0f / 256.0f), &s, &c);
        g_Tfh[idx] = make_float2(c, s);
        g_Tih[idx] = make_float2(c, -s);
    }
}

// ---------------- spectral-weight transpose: (l,i,o,kx,ky) -> (l,m,i,o) ----------------
__global__ void k_wt(const float* __restrict__ w1r, const float* __restrict__ w1i,
                     const float* __restrict__ w2r, const float* __restrict__ w2i) {
    int tid = blockIdx.x * blockDim.x + threadIdx.x;
    if (tid >= NLAY * 512 * WID * WID) return;
    int o   = tid & 63;
    int i   = (tid >> 6) & 63;
    int m   = (tid >> 12) & 511;
    int l   = tid >> 21;
    int kxi = m >> 4;
    int ky  = m & 15;
    int kk  = (kxi & 15) * 16 + ky;
    size_t src = ((size_t)(l * 64 + i) * 64 + o) * 256 + kk;
    float r, im;
    if (kxi < 16) { r = w1r[src]; im = w1i[src]; }
    else          { r = w2r[src]; im = w2i[src]; }
    g_Wt[tid] = make_float2(r, im);
}

// ---------------- fc0 lift: 20 -> 64 per pixel (packed pairs) ----------------
__global__ void __launch_bounds__(256) k_fc0(const float* __restrict__ x,
                                             const float* __restrict__ w,
                                             const float* __restrict__ bias) {
    __shared__ ull wp[CIN * 32];   // wp[c*32+d2] = (w[2d2][c], w[2d2+1][c])
    __shared__ ull bp[32];
    int t = threadIdx.x;
    for (int k = t; k < CIN * 32; k += 256) {
        int d2 = k & 31, c = k >> 5;
        wp[c * 32 + d2] = pk(w[(2 * d2) * CIN + c], w[(2 * d2 + 1) * CIN + c]);
    }
    if (t < 32) bp[t] = pk(bias[2 * t], bias[2 * t + 1]);
    __syncthreads();
    int p  = blockIdx.x * 256 + t;
    int b  = p >> 16;
    int sp = p & 65535;
    ull xx[CIN];
#pragma unroll
    for (int c = 0; c < CIN; c++) {
        float v = x[((size_t)(b * CIN + c) << 16) + sp];
        xx[c] = pk(v, v);
    }
#pragma unroll
    for (int d2 = 0; d2 < 32; d2++) {
        ull a = bp[d2];
#pragma unroll
        for (int c = 0; c < CIN; c++) a = ff2(xx[c], wp[c * 32 + d2], a);
        float2 f = upk(a);
        g_h0[((size_t)(b * WID + 2 * d2) << 16) + sp]     = f.x;
        g_h0[((size_t)(b * WID + 2 * d2 + 1) << 16) + sp] = f.y;
    }
}

// ---------------- forward DFT along w: register-tiled GEMM, f32x2 ----------------
// grid 512, block 256. Block covers 512 rows. Thread: 4 rows x 8 ky (packed complex).
__global__ void __launch_bounds__(256, 2) k_dftw(const float* __restrict__ hin) {
    extern __shared__ char sm[];
    ull*   Tsh = (ull*)sm;                 // 4096 u64 = 32 KB, layout [ky*256+w]
    float* xsT = (float*)(sm + 32768);     // [16][520] = 33.3 KB (transposed chunk)
    int t = threadIdx.x;
    for (int k = t; k < 4096; k += 256) Tsh[k] = ((const ull*)g_Tfw)[k];
    int kyh = t & 1;           // ky half: 0 -> ky 0..7, 1 -> ky 8..15
    int rg  = t >> 1;          // row group 0..127 (4 rows each)
    size_t rbase = (size_t)blockIdx.x * 512;

    ull acc[4][8];
#pragma unroll
    for (int j = 0; j < 4; j++)
#pragma unroll
        for (int k = 0; k < 8; k++) acc[j][k] = 0ULL;

    for (int c = 0; c < 16; c++) {
        __syncthreads();
        for (int k = t; k < 8192; k += 256) {
            int row = k >> 4, wl = k & 15;
            xsT[wl * 520 + row] = hin[(rbase + row) * 256 + c * 16 + wl];
        }
        __syncthreads();
#pragma unroll
        for (int wl = 0; wl < 16; wl++) {
            float4 v4 = *(const float4*)&xsT[wl * 520 + rg * 4];
            ull vv0 = pk(v4.x, v4.x), vv1 = pk(v4.y, v4.y);
            ull vv2 = pk(v4.z, v4.z), vv3 = pk(v4.w, v4.w);
            int w = c * 16 + wl;
#pragma unroll
            for (int kk = 0; kk < 8; kk++) {
                ull tw = Tsh[(kyh * 8 + kk) * 256 + w];
                acc[0][kk] = ff2(vv0, tw, acc[0][kk]);
                acc[1][kk] = ff2(vv1, tw, acc[1][kk]);
                acc[2][kk] = ff2(vv2, tw, acc[2][kk]);
                acc[3][kk] = ff2(vv3, tw, acc[3][kk]);
            }
        }
    }
    ull* out = (ull*)g_Fw;
#pragma unroll
    for (int j = 0; j < 4; j++) {
        size_t r = rbase + rg * 4 + j;
#pragma unroll
        for (int kk = 0; kk < 8; kk++)
            out[r * 16 + kyh * 8 + kk] = acc[j][kk];
    }
}

// ---------------- forward DFT along h: block per (b,c) ----------------
__global__ void k_dfth() {
    extern __shared__ float2 sh[];
    float2* Fsh = sh;            // 4096 = 256*16
    float2* Tsh = sh + 4096;     // 8192 = 32*256
    int t = threadIdx.x;
    int bc = blockIdx.x;
    for (int k = t; k < 4096; k += 256) Fsh[k] = g_Fw[(size_t)bc * 4096 + k];
    for (int k = t; k < 8192; k += 256) Tsh[k] = g_Tfh[k];
    __syncthreads();
#pragma unroll
    for (int mm = 0; mm < 2; mm++) {
        int m = t + mm * 256;
        int kxi = m >> 4, ky = m & 15;
        float sr = 0.f, si = 0.f;
        for (int h = 0; h < 256; h++) {
            float2 f  = Fsh[h * 16 + ky];
            float2 tw = Tsh[kxi * 256 + h];
            sr = fmaf(f.x, tw.x, fmaf(-f.y, tw.y, sr));
            si = fmaf(f.x, tw.y, fmaf( f.y, tw.x, si));
        }
        g_Fm[(size_t)bc * 512 + m] = make_float2(sr, si);
    }
}

// ---------------- channel mixing: block per mode ----------------
__global__ void k_mix(int layer) {
    __shared__ float2 Wm[WID * WID];   // 32 KB
    __shared__ float2 Fsh[BB * WID];   //  8 KB
    int t = threadIdx.x;
    int m = blockIdx.x;
    const float2* wsrc = g_Wt + ((size_t)layer * 512 + m) * 4096;
    for (int k = t; k < 4096; k += 256) Wm[k] = wsrc[k];
    for (int k = t; k < 1024; k += 256) {
        int b = k >> 6, i = k & 63;
        Fsh[k] = g_Fm[(size_t)(b * 64 + i) * 512 + m];
    }
    __syncthreads();
#pragma unroll
    for (int u = 0; u < 4; u++) {
        int outi = t + u * 256;
        int b = outi >> 6, o = outi & 63;
        float sr = 0.f, si = 0.f;
#pragma unroll 8
        for (int i = 0; i < 64; i++) {
            float2 f = Fsh[b * 64 + i];
            float2 w = Wm[i * 64 + o];
            sr = fmaf(f.x, w.x, fmaf(-f.y, w.y, sr));
            si = fmaf(f.x, w.y, fmaf( f.y, w.x, si));
        }
        g_Gm[(size_t)(b * 64 + o) * 512 + m] = make_float2(sr, si);
    }
}

// ---------------- inverse transform along h: block per (b,c) ----------------
__global__ void k_idfth() {
    extern __shared__ float2 sh[];
    float2* Gsh = sh;            // 512
    float2* Tsh = sh + 512;      // 8192
    int t = threadIdx.x;
    int bc = blockIdx.x;
    for (int k = t; k < 512; k += 256) Gsh[k] = g_Gm[(size_t)bc * 512 + k];
    for (int k = t; k < 8192; k += 256) Tsh[k] = g_Tih[k];
    __syncthreads();
    int h = t;
    float orr[16], oii[16];
#pragma unroll
    for (int k = 0; k < 16; k++) { orr[k] = 0.f; oii[k] = 0.f; }
    for (int kxi = 0; kxi < 32; kxi++) {
        float2 tw = Tsh[kxi * 256 + h];
#pragma unroll
        for (int ky = 0; ky < 16; ky++) {
            float2 g = Gsh[kxi * 16 + ky];
            orr[ky] = fmaf(g.x, tw.x, fmaf(-g.y, tw.y, orr[ky]));
            oii[ky] = fmaf(g.x, tw.y, fmaf( g.y, tw.x, oii[ky]));
        }
    }
    float2* outp = g_Gw + ((size_t)bc * 256 + h) * 16;
#pragma unroll
    for (int ky = 0; ky < 16; ky++) outp[ky] = make_float2(orr[ky], oii[ky]);
}

// ---------------- fused: inverse-w synthesis + pointwise conv + bias + gelu ----------------
// block 256 = (og 0..3) x (tw 0..63); thread handles 4 pixels x 16 out-channels.
__global__ void __launch_bounds__(256, 2)
k_fused(const float* __restrict__ hin, float* __restrict__ hout,
        const float* __restrict__ pww, const float* __restrict__ pwb, int dogelu) {
    __shared__ ull wdup[4096];   // 32 KB: (w,w) pairs, [o*64+i]
    __shared__ ull Gd[1024];     // 8 KB: [o*16+ky] = (2gx,-2gy) (ky=0: (gx,0))
    __shared__ float bsh[64];

    int t = threadIdx.x;
    int b   = blockIdx.x >> 8;
    int row = blockIdx.x & 255;

    for (int k = t; k < 4096; k += 256) { float w = pww[k]; wdup[k] = pk(w, w); }
    for (int k = t; k < 1024; k += 256) {
        int o = k >> 4, ky = k & 15;
        float2 g = g_Gw[(((size_t)(b * 64 + o)) * 256 + row) * 16 + ky];
        Gd[k] = (ky == 0) ? pk(g.x, 0.f) : pk(2.f * g.x, -2.f * g.y);
    }
    if (t < 64) bsh[t] = pwb[t];
    __syncthreads();

    int tw = t & 63, og = t >> 6;
    ull acc[16][2];
#pragma unroll
    for (int oo = 0; oo < 16; oo++) {
        float bv = bsh[og * 16 + oo];
        acc[oo][0] = pk(bv, bv);
        acc[oo][1] = pk(bv, bv);
    }

    size_t base = ((size_t)(b * 64) << 16) + (row << 8) + tw * 4;
    for (int i = 0; i < 64; i++) {
        ulonglong2 xv = *(const ulonglong2*)(hin + base + ((size_t)i << 16));
#pragma unroll
        for (int oo = 0; oo < 16; oo++) {
            ull wd = wdup[(og * 16 + oo) * 64 + i];
            acc[oo][0] = ff2(xv.x, wd, acc[oo][0]);
            acc[oo][1] = ff2(xv.y, wd, acc[oo][1]);
        }
    }

    const float invn = 1.0f / 65536.0f;
#pragma unroll
    for (int q = 0; q < 4; q++) {
        int w = tw * 4 + q;
        float s1, c1;
        sincosf(TWO_PI * (float)w * (1.0f / 256.0f), &s1, &c1);
        ull tww[16];
        tww[0] = pk(1.f, 0.f);
        float cr = c1, ci = s1;
        tww[1] = pk(cr, ci);
#pragma unroll
        for (int k = 2; k < 16; k++) {
            float nr = cr * c1 - ci * s1;
            float ni = cr * s1 + ci * c1;
            cr = nr; ci = ni;
            tww[k] = pk(cr, ci);
        }
        int p = q >> 1, lane = q & 1;
#pragma unroll
        for (int oo = 0; oo < 16; oo++) {
            const ull* g = &Gd[(og * 16 + oo) << 4];
            ull xa = 0ULL;
#pragma unroll
            for (int ky = 0; ky < 16; ky++) xa = ff2(g[ky], tww[ky], xa);
            float2 xf = upk(xa);
            float x1 = xf.x + xf.y;        // (sum 2gx*cos) + (sum -2gy*sin); ky=0 -> gx
            float2 a = upk(acc[oo][p]);
            float v = fmaf(x1, invn, lane ? a.y : a.x);
            if (dogelu) v = gelu_fast(v);
            if (lane) a.y = v; else a.x = v;
            acc[oo][p] = pk(a.x, a.y);
        }
    }

#pragma unroll
    for (int oo = 0; oo < 16; oo++) {
        int o = og * 16 + oo;
        ulonglong2 st; st.x = acc[oo][0]; st.y = acc[oo][1];
        *(ulonglong2*)(hout + ((size_t)(b * 64 + o) << 16) + (row << 8) + tw * 4) = st;
    }
}

// ---------------- fused projection: 64 -> 128 (gelu) -> 20, packed pairs ----------------
__global__ void __launch_bounds__(256, 2)
k_final(const float* __restrict__ hin, float* __restrict__ out,
        const float* __restrict__ w1, const float* __restrict__ b1,
        const float* __restrict__ w2, const float* __restrict__ b2) {
    __shared__ ull w1p[FCH * 32];     // 32 KB: u64 view of w1 (pairs over in-ch)
    __shared__ ull w2t[FCH * 10];     // 10 KB: [j*10+o2] = (w2[2o2][j], w2[2o2+1][j])
    __shared__ float b1sh[FCH];
    __shared__ ull b2p[10];
    int t = threadIdx.x;
    for (int k = t; k < FCH * 32; k += 256) w1p[k] = ((const ull*)w1)[k];
    for (int k = t; k < FCH * 10; k += 256) {
        int o2 = k >> 7, j = k & 127;
        w2t[j * 10 + o2] = pk(w2[(2 * o2) * FCH + j], w2[(2 * o2 + 1) * FCH + j]);
    }
    if (t < FCH) b1sh[t] = b1[t];
    if (t < 10)  b2p[t] = pk(b2[2 * t], b2[2 * t + 1]);
    __syncthreads();

    int b   = blockIdx.x >> 8;
    int row = blockIdx.x & 255;
    size_t sp = ((size_t)row << 8) + t;
    size_t base = ((size_t)(b * WID) << 16) + sp;
    ull xv[32];
#pragma unroll
    for (int i2 = 0; i2 < 32; i2++)
        xv[i2] = pk(hin[base + ((size_t)(2 * i2) << 16)],
                    hin[base + ((size_t)(2 * i2 + 1) << 16)]);
    ull acc[10];
#pragma unroll
    for (int o2 = 0; o2 < 10; o2++) acc[o2] = b2p[o2];

    for (int j = 0; j < FCH; j++) {
        ull h2 = 0ULL;
#pragma unroll
        for (int i2 = 0; i2 < 32; i2++) h2 = ff2(xv[i2], w1p[j * 32 + i2], h2);
        float2 hf = upk(h2);
        float hv = gelu_fast(hf.x + hf.y + b1sh[j]);
        ull hh = pk(hv, hv);
#pragma unroll
        for (int o2 = 0; o2 < 10; o2++) acc[o2] = ff2(hh, w2t[j * 10 + o2], acc[o2]);
    }
#pragma unroll
    for (int o2 = 0; o2 < 10; o2++) {
        float2 a = upk(acc[o2]);
        out[((size_t)(b * CO + 2 * o2) << 16) + sp]     = a.x;
        out[((size_t)(b * CO + 2 * o2 + 1) << 16) + sp] = a.y;
    }
}

// ---------------- orchestration ----------------
extern "C" void kernel_launch(void* const* d_in, const int* in_sizes, int n_in,
                              void* d_out, int out_size) {
    const float* x    = (const float*)d_in[0];
    const float* w1r  = (const float*)d_in[1];
    const float* w1i  = (const float*)d_in[2];
    const float* w2r  = (const float*)d_in[3];
    const float* w2i  = (const float*)d_in[4];
    const float* pww  = (const float*)d_in[5];
    const float* pwb  = (const float*)d_in[6];
    const float* fc0w = (const float*)d_in[7];
    const float* fc0b = (const float*)d_in[8];
    const float* fc1w = (const float*)d_in[9];
    const float* fc1b = (const float*)d_in[10];
    const float* fc2w = (const float*)d_in[11];
    const float* fc2b = (const float*)d_in[12];
    float* out = (float*)d_out;

    cudaFuncSetAttribute(k_dftw,  cudaFuncAttributeMaxDynamicSharedMemorySize, 66048);
    cudaFuncSetAttribute(k_dfth,  cudaFuncAttributeMaxDynamicSharedMemorySize, 98304);
    cudaFuncSetAttribute(k_idfth, cudaFuncAttributeMaxDynamicSharedMemorySize, 69632);

    void *p0, *p1;
    cudaGetSymbolAddress(&p0, g_h0);
    cudaGetSymbolAddress(&p1, g_h1);
    float* hb[2] = {(float*)p0, (float*)p1};

    k_twiddle<<<32, 256>>>();
    k_wt<<<(NLAY * 512 * WID * WID) / 256, 256>>>(w1r, w1i, w2r, w2i);
    k_fc0<<<NPIX / 256, 256>>>(x, fc0w, fc0b);

    for (int l = 0; l < NLAY; l++) {
        const float* hi = hb[l & 1];
        float*       ho = hb[(l + 1) & 1];
        k_dftw<<<512, 256, 66048>>>(hi);
        k_dfth<<<1024, 256, 98304>>>();
        k_mix<<<512, 256>>>(l);
        k_idfth<<<1024, 256, 69632>>>();
        k_fused<<<4096, 256>>>(hi, ho, pww + (size_t)l * WID * WID,
                               pwb + (size_t)l * WID, (l < NLAY - 1) ? 1 : 0);
    }
    k_final<<<4096, 256>>>(hb[0], out, fc1w, fc1b, fc2w, fc2b);
}

// round 5
// speedup vs baseline: 2.3946x; 1.3411x over previous
#include <cuda_runtime.h>
#include <math.h>

#define BB 16
#define CIN 20
#define HH 256
#define WW 256
#define WID 64
#define M1V 16
#define M2V 16
#define NLAY 4
#define FCH 128
#define CO 20
#define HW 65536
#define NPIX (BB*HW)

#define TWO_PI 6.28318530717958647692f

typedef unsigned long long ull;

// ---------------- scratch (device globals; no allocations allowed) ----------------
__device__ float  g_h0[(size_t)BB*WID*HW];            // 268 MB ping
__device__ float  g_h1[(size_t)BB*WID*HW];            // 268 MB pong
__device__ float2 g_Fw[(size_t)BB*WID*HH*M2V];        // (b,c,h,ky)  33.5 MB
__device__ float2 g_Fm[(size_t)BB*WID*32*M2V];        // (b,c,kxi,ky) 4 MB
__device__ float2 g_Gm[(size_t)BB*WID*32*M2V];        // 4 MB
__device__ float2 g_Gw[(size_t)BB*WID*HH*M2V];        // (b,c,h,ky)  33.5 MB
__device__ float2 g_Wt[(size_t)NLAY*512*WID*WID];     // (l,m,i,o)   67 MB
__device__ float2 g_Tfw[M2V*WW];                      // e^{-2pi i ky w/256}, [ky*256+w]
__device__ ull    g_TfwT[WW*M2V];                     // same, transposed [w*16+ky]
__device__ ull    g_Tsyn[WW*M2V];                     // e^{+2pi i ky w/256}, [w*16+ky]
__device__ float2 g_Tfh[32*HH];                       // e^{-2pi i kx h/256}, kx in R
__device__ float2 g_Tih[32*HH];                       // conj of above

// ---- packed f32x2 helpers ----
__device__ __forceinline__ ull ff2(ull a, ull b, ull c) {
    ull d; asm("fma.rn.f32x2 %0,%1,%2,%3;" : "=l"(d) : "l"(a), "l"(b), "l"(c)); return d;
}
__device__ __forceinline__ ull pk(float x, float y) {
    ull d; asm("mov.b64 %0,{%1,%2};" : "=l"(d) : "f"(x), "f"(y)); return d;
}
__device__ __forceinline__ float2 upk(ull u) {
    float2 f; asm("mov.b64 {%0,%1},%2;" : "=f"(f.x), "=f"(f.y) : "l"(u)); return f;
}

// ---- fast erf-based gelu (Abramowitz-Stegun 7.1.26, |eps|<=1.5e-7) ----
__device__ __forceinline__ float gelu_fast(float v) {
    float z  = 0.70710678118654752440f * v;
    float az = fabsf(z);
    float t  = __fdividef(1.0f, fmaf(0.3275911f, az, 1.0f));
    float e  = __expf(-az * az);
    float p  = t * (0.254829592f + t * (-0.284496736f + t * (1.421413741f +
               t * (-1.453152027f + t * 1.061405429f))));
    float er = fmaf(-p, e, 1.0f);
    er = copysignf(er, z);
    return 0.5f * v * (1.0f + er);
}

// ---------------- twiddle init ----------------
__global__ void k_twiddle() {
    int idx = blockIdx.x * blockDim.x + threadIdx.x;   // 8192 threads
    if (idx < M2V * WW) {
        int ky = idx >> 8, w = idx & 255;
        int ph = (ky * w) & 255;                       // exact phase mod 256
        float s, c;
        sincosf(-TWO_PI * (float)ph * (1.0f / 256.0f), &s, &c);
        g_Tfw[idx] = make_float2(c, s);
        g_TfwT[w * 16 + ky] = pk(c, s);
        g_Tsyn[w * 16 + ky] = pk(c, -s);               // e^{+i theta}
    }
    if (idx < 32 * HH) {
        int kxi = idx >> 8, h = idx & 255;
        int kx = (kxi < 16) ? kxi : (224 + kxi);       // rows 240..255
        int ph = (kx * h) & 255;
        float s, c;
        sincosf(-TWO_PI * (float)ph * (1.0f / 256.0f), &s, &c);
        g_Tfh[idx] = make_float2(c, s);
        g_Tih[idx] = make_float2(c, -s);
    }
}

// ---------------- spectral-weight transpose: (l,i,o,kx,ky) -> (l,m,i,o) ----------------
__global__ void k_wt(const float* __restrict__ w1r, const float* __restrict__ w1i,
                     const float* __restrict__ w2r, const float* __restrict__ w2i) {
    int tid = blockIdx.x * blockDim.x + threadIdx.x;
    if (tid >= NLAY * 512 * WID * WID) return;
    int o   = tid & 63;
    int i   = (tid >> 6) & 63;
    int m   = (tid >> 12) & 511;
    int l   = tid >> 21;
    int kxi = m >> 4;
    int ky  = m & 15;
    int kk  = (kxi & 15) * 16 + ky;
    size_t src = ((size_t)(l * 64 + i) * 64 + o) * 256 + kk;
    float r, im;
    if (kxi < 16) { r = w1r[src]; im = w1i[src]; }
    else          { r = w2r[src]; im = w2i[src]; }
    g_Wt[tid] = make_float2(r, im);
}

// ---------------- fc0 lift: 20 -> 64 per pixel (packed pairs) ----------------
__global__ void __launch_bounds__(256) k_fc0(const float* __restrict__ x,
                                             const float* __restrict__ w,
                                             const float* __restrict__ bias) {
    __shared__ ull wp[CIN * 32];   // wp[c*32+d2] = (w[2d2][c], w[2d2+1][c])
    __shared__ ull bp[32];
    int t = threadIdx.x;
    for (int k = t; k < CIN * 32; k += 256) {
        int d2 = k & 31, c = k >> 5;
        wp[c * 32 + d2] = pk(w[(2 * d2) * CIN + c], w[(2 * d2 + 1) * CIN + c]);
    }
    if (t < 32) bp[t] = pk(bias[2 * t], bias[2 * t + 1]);
    __syncthreads();
    int p  = blockIdx.x * 256 + t;
    int b  = p >> 16;
    int sp = p & 65535;
    ull xx[CIN];
#pragma unroll
    for (int c = 0; c < CIN; c++) {
        float v = x[((size_t)(b * CIN + c) << 16) + sp];
        xx[c] = pk(v, v);
    }
#pragma unroll
    for (int d2 = 0; d2 < 32; d2++) {
        ull a = bp[d2];
#pragma unroll
        for (int c = 0; c < CIN; c++) a = ff2(xx[c], wp[c * 32 + d2], a);
        float2 f = upk(a);
        g_h0[((size_t)(b * WID + 2 * d2) << 16) + sp]     = f.x;
        g_h0[((size_t)(b * WID + 2 * d2 + 1) << 16) + sp] = f.y;
    }
}

// ---------------- forward DFT along w: 2 rows x 8 ky per thread, LDS.128 twiddles ----
// grid 1024, block 256. Block covers 256 rows.
__global__ void __launch_bounds__(256) k_dftw(const float* __restrict__ hin) {
    extern __shared__ char sm[];
    ull*   TshT = (ull*)sm;                // 4096 ull = 32 KB, [w*16+ky]
    float* xsT  = (float*)(sm + 32768);    // [16][258] = 16.5 KB
    int t = threadIdx.x;
    for (int k = t; k < 4096; k += 256) TshT[k] = g_TfwT[k];
    int kyh = t & 1;           // ky half
    int rg  = t >> 1;          // row pair 0..127
    size_t rbase = (size_t)blockIdx.x * 256;

    ull acc[2][8];
#pragma unroll
    for (int j = 0; j < 2; j++)
#pragma unroll
        for (int k = 0; k < 8; k++) acc[j][k] = 0ULL;

    for (int c = 0; c < 16; c++) {
        __syncthreads();
        for (int k = t; k < 4096; k += 256) {
            int wl = k & 15, row = k >> 4;
            xsT[wl * 258 + row] = hin[(rbase + row) * 256 + c * 16 + wl];
        }
        __syncthreads();
#pragma unroll
        for (int wl = 0; wl < 16; wl++) {
            float2 v = *(const float2*)&xsT[wl * 258 + rg * 2];
            ull v0 = pk(v.x, v.x), v1 = pk(v.y, v.y);
            const ulonglong2* tp =
                (const ulonglong2*)&TshT[(c * 16 + wl) * 16 + kyh * 8];
#pragma unroll
            for (int q = 0; q < 4; q++) {
                ulonglong2 tw = tp[q];
                acc[0][2 * q]     = ff2(v0, tw.x, acc[0][2 * q]);
                acc[0][2 * q + 1] = ff2(v0, tw.y, acc[0][2 * q + 1]);
                acc[1][2 * q]     = ff2(v1, tw.x, acc[1][2 * q]);
                acc[1][2 * q + 1] = ff2(v1, tw.y, acc[1][2 * q + 1]);
            }
        }
    }
    ull* outp = (ull*)g_Fw;
#pragma unroll
    for (int j = 0; j < 2; j++) {
        size_t r = rbase + rg * 2 + j;
        ulonglong2* op = (ulonglong2*)(outp + r * 16 + kyh * 8);
#pragma unroll
        for (int q = 0; q < 4; q++) {
            ulonglong2 st; st.x = acc[j][2 * q]; st.y = acc[j][2 * q + 1];
            op[q] = st;
        }
    }
}

// ---------------- forward DFT along h: block per (b,c) ----------------
__global__ void k_dfth() {
    extern __shared__ float2 sh[];
    float2* Fsh = sh;            // 4096 = 256*16
    float2* Tsh = sh + 4096;     // 8192 = 32*256
    int t = threadIdx.x;
    int bc = blockIdx.x;
    for (int k = t; k < 4096; k += 256) Fsh[k] = g_Fw[(size_t)bc * 4096 + k];
    for (int k = t; k < 8192; k += 256) Tsh[k] = g_Tfh[k];
    __syncthreads();
#pragma unroll
    for (int mm = 0; mm < 2; mm++) {
        int m = t + mm * 256;
        int kxi = m >> 4, ky = m & 15;
        float sr = 0.f, si = 0.f;
        for (int h = 0; h < 256; h++) {
            float2 f  = Fsh[h * 16 + ky];
            float2 tw = Tsh[kxi * 256 + h];
            sr = fmaf(f.x, tw.x, fmaf(-f.y, tw.y, sr));
            si = fmaf(f.x, tw.y, fmaf( f.y, tw.x, si));
        }
        g_Fm[(size_t)bc * 512 + m] = make_float2(sr, si);
    }
}

// ---------------- channel mixing: block per mode ----------------
__global__ void k_mix(int layer) {
    __shared__ float2 Wm[WID * WID];   // 32 KB
    __shared__ float2 Fsh[BB * WID];   //  8 KB
    int t = threadIdx.x;
    int m = blockIdx.x;
    const float2* wsrc = g_Wt + ((size_t)layer * 512 + m) * 4096;
    for (int k = t; k < 4096; k += 256) Wm[k] = wsrc[k];
    for (int k = t; k < 1024; k += 256) {
        int b = k >> 6, i = k & 63;
        Fsh[k] = g_Fm[(size_t)(b * 64 + i) * 512 + m];
    }
    __syncthreads();
#pragma unroll
    for (int u = 0; u < 4; u++) {
        int outi = t + u * 256;
        int b = outi >> 6, o = outi & 63;
        float sr = 0.f, si = 0.f;
#pragma unroll 8
        for (int i = 0; i < 64; i++) {
            float2 f = Fsh[b * 64 + i];
            float2 w = Wm[i * 64 + o];
            sr = fmaf(f.x, w.x, fmaf(-f.y, w.y, sr));
            si = fmaf(f.x, w.y, fmaf( f.y, w.x, si));
        }
        g_Gm[(size_t)(b * 64 + o) * 512 + m] = make_float2(sr, si);
    }
}

// ---------------- inverse transform along h: packed f32x2, dup-pair G ----------------
__global__ void k_idfth() {
    extern __shared__ char shb[];
    ulonglong2* Gsh2 = (ulonglong2*)shb;          // 512 * 16B = 8 KB
    float2*     Tsh  = (float2*)(shb + 8192);     // 8192 * 8B = 64 KB
    int t = threadIdx.x;
    int bc = blockIdx.x;
    for (int k = t; k < 512; k += 256) {
        float2 g = g_Gm[(size_t)bc * 512 + k];
        ulonglong2 d; d.x = pk(g.x, g.x); d.y = pk(g.y, g.y);
        Gsh2[k] = d;
    }
    for (int k = t; k < 8192; k += 256) Tsh[k] = g_Tih[k];
    __syncthreads();
    int h = t;
    ull acc[16];
#pragma unroll
    for (int k = 0; k < 16; k++) acc[k] = 0ULL;
    for (int kxi = 0; kxi < 32; kxi++) {
        float2 tw = Tsh[kxi * 256 + h];
        ull t1 = pk(tw.x, tw.y);
        ull t2 = pk(-tw.y, tw.x);
        const ulonglong2* gp = &Gsh2[kxi * 16];
#pragma unroll
        for (int ky = 0; ky < 16; ky++) {
            ulonglong2 g = gp[ky];
            acc[ky] = ff2(g.x, t1, acc[ky]);
            acc[ky] = ff2(g.y, t2, acc[ky]);
        }
    }
    ull* outp = (ull*)(g_Gw + ((size_t)bc * 256 + h) * 16);
#pragma unroll
    for (int ky = 0; ky < 16; ky++) outp[ky] = acc[ky];
}

// ---------------- fused: inverse-w synthesis + pointwise conv + bias + gelu ----------------
// block 256 = (og 0..3) x (tw 0..63); thread handles 4 pixels x 16 out-channels.
__global__ void __launch_bounds__(256, 2)
k_fused(const float* __restrict__ hin, float* __restrict__ hout,
        const float* __restrict__ pww, const float* __restrict__ pwb, int dogelu) {
    __shared__ ull wdupT[4096];  // 32 KB: (w,w) pairs, TRANSPOSED [i*64+o]
    __shared__ ull Gd[1024];     // 8 KB: [o*16+ky] = (2gx,-2gy) (ky=0: (gx,0))
    __shared__ float bsh[64];

    int t = threadIdx.x;
    int b   = blockIdx.x >> 8;
    int row = blockIdx.x & 255;

    for (int k = t; k < 4096; k += 256) {
        int o = k & 63, i = k >> 6;
        float w = pww[o * 64 + i];
        wdupT[k] = pk(w, w);
    }
    for (int k = t; k < 1024; k += 256) {
        int o = k >> 4, ky = k & 15;
        float2 g = g_Gw[(((size_t)(b * 64 + o)) * 256 + row) * 16 + ky];
        Gd[k] = (ky == 0) ? pk(g.x, 0.f) : pk(2.f * g.x, -2.f * g.y);
    }
    if (t < 64) bsh[t] = pwb[t];
    __syncthreads();

    int tw = t & 63, og = t >> 6;
    ull acc[16][2];
#pragma unroll
    for (int oo = 0; oo < 16; oo++) {
        float bv = bsh[og * 16 + oo];
        acc[oo][0] = pk(bv, bv);
        acc[oo][1] = pk(bv, bv);
    }

    size_t base = ((size_t)(b * 64) << 16) + (row << 8) + tw * 4;
    for (int i = 0; i < 64; i++) {
        ulonglong2 xv = *(const ulonglong2*)(hin + base + ((size_t)i << 16));
        const ulonglong2* wp = (const ulonglong2*)&wdupT[i * 64 + og * 16];
#pragma unroll
        for (int j = 0; j < 8; j++) {
            ulonglong2 wd = wp[j];
            acc[2 * j][0]     = ff2(xv.x, wd.x, acc[2 * j][0]);
            acc[2 * j][1]     = ff2(xv.y, wd.x, acc[2 * j][1]);
            acc[2 * j + 1][0] = ff2(xv.x, wd.y, acc[2 * j + 1][0]);
            acc[2 * j + 1][1] = ff2(xv.y, wd.y, acc[2 * j + 1][1]);
        }
    }

    const float invn = 1.0f / 65536.0f;
#pragma unroll
    for (int q = 0; q < 4; q++) {
        int w = tw * 4 + q;
        const ulonglong2* tp = (const ulonglong2*)&g_Tsyn[w * 16];
        ulonglong2 tww[8];
#pragma unroll
        for (int j = 0; j < 8; j++) tww[j] = tp[j];
        int p = q >> 1, lane = q & 1;
#pragma unroll
        for (int oo = 0; oo < 16; oo++) {
            const ulonglong2* gp = (const ulonglong2*)&Gd[(og * 16 + oo) << 4];
            ull xa = 0ULL;
#pragma unroll
            for (int j = 0; j < 8; j++) {
                ulonglong2 g = gp[j];
                xa = ff2(g.x, tww[j].x, xa);
                xa = ff2(g.y, tww[j].y, xa);
            }
            float2 xf = upk(xa);
            float x1 = xf.x + xf.y;    // (sum 2gx*cos) + (sum -2gy*sin); ky=0 -> gx
            float2 a = upk(acc[oo][p]);
            float v = fmaf(x1, invn, lane ? a.y : a.x);
            if (dogelu) v = gelu_fast(v);
            if (lane) a.y = v; else a.x = v;
            acc[oo][p] = pk(a.x, a.y);
        }
    }

#pragma unroll
    for (int oo = 0; oo < 16; oo++) {
        int o = og * 16 + oo;
        ulonglong2 st; st.x = acc[oo][0]; st.y = acc[oo][1];
        *(ulonglong2*)(hout + ((size_t)(b * 64 + o) << 16) + (row << 8) + tw * 4) = st;
    }
}

// ---------------- fused projection: 64 -> 128 (gelu) -> 20, packed pairs ----------------
__global__ void __launch_bounds__(256, 2)
k_final(const float* __restrict__ hin, float* __restrict__ out,
        const float* __restrict__ w1, const float* __restrict__ b1,
        const float* __restrict__ w2, const float* __restrict__ b2) {
    __shared__ ull w1p[FCH * 32];     // 32 KB: u64 view of w1 (pairs over in-ch)
    __shared__ ull w2t[FCH * 10];     // 10 KB: [j*10+o2] = (w2[2o2][j], w2[2o2+1][j])
    __shared__ float b1sh[FCH];
    __shared__ ull b2p[10];
    int t = threadIdx.x;
    for (int k = t; k < FCH * 32; k += 256) w1p[k] = ((const ull*)w1)[k];
    for (int k = t; k < FCH * 10; k += 256) {
        int o2 = k >> 7, j = k & 127;
        w2t[j * 10 + o2] = pk(w2[(2 * o2) * FCH + j], w2[(2 * o2 + 1) * FCH + j]);
    }
    if (t < FCH) b1sh[t] = b1[t];
    if (t < 10)  b2p[t] = pk(b2[2 * t], b2[2 * t + 1]);
    __syncthreads();

    int b   = blockIdx.x >> 8;
    int row = blockIdx.x & 255;
    size_t sp = ((size_t)row << 8) + t;
    size_t base = ((size_t)(b * WID) << 16) + sp;
    ull xv[32];
#pragma unroll
    for (int i2 = 0; i2 < 32; i2++)
        xv[i2] = pk(hin[base + ((size_t)(2 * i2) << 16)],
                    hin[base + ((size_t)(2 * i2 + 1) << 16)]);
    ull acc[10];
#pragma unroll
    for (int o2 = 0; o2 < 10; o2++) acc[o2] = b2p[o2];

    for (int j = 0; j < FCH; j++) {
        const ulonglong2* wp = (const ulonglong2*)&w1p[j * 32];
        ull h2 = 0ULL;
#pragma unroll
        for (int k = 0; k < 16; k++) {
            ulonglong2 u = wp[k];
            h2 = ff2(xv[2 * k], u.x, h2);
            h2 = ff2(xv[2 * k + 1], u.y, h2);
        }
        float2 hf = upk(h2);
        float hv = gelu_fast(hf.x + hf.y + b1sh[j]);
        ull hh = pk(hv, hv);
        const ulonglong2* w2p = (const ulonglong2*)&w2t[j * 10];
#pragma unroll
        for (int k = 0; k < 5; k++) {
            ulonglong2 u = w2p[k];
            acc[2 * k]     = ff2(hh, u.x, acc[2 * k]);
            acc[2 * k + 1] = ff2(hh, u.y, acc[2 * k + 1]);
        }
    }
#pragma unroll
    for (int o2 = 0; o2 < 10; o2++) {
        float2 a = upk(acc[o2]);
        out[((size_t)(b * CO + 2 * o2) << 16) + sp]     = a.x;
        out[((size_t)(b * CO + 2 * o2 + 1) << 16) + sp] = a.y;
    }
}

// ---------------- orchestration ----------------
extern "C" void kernel_launch(void* const* d_in, const int* in_sizes, int n_in,
                              void* d_out, int out_size) {
    const float* x    = (const float*)d_in[0];
    const float* w1r  = (const float*)d_in[1];
    const float* w1i  = (const float*)d_in[2];
    const float* w2r  = (const float*)d_in[3];
    const float* w2i  = (const float*)d_in[4];
    const float* pww  = (const float*)d_in[5];
    const float* pwb  = (const float*)d_in[6];
    const float* fc0w = (const float*)d_in[7];
    const float* fc0b = (const float*)d_in[8];
    const float* fc1w = (const float*)d_in[9];
    const float* fc1b = (const float*)d_in[10];
    const float* fc2w = (const float*)d_in[11];
    const float* fc2b = (const float*)d_in[12];
    float* out = (float*)d_out;

    cudaFuncSetAttribute(k_dftw,  cudaFuncAttributeMaxDynamicSharedMemorySize, 49280);
    cudaFuncSetAttribute(k_dfth,  cudaFuncAttributeMaxDynamicSharedMemorySize, 98304);
    cudaFuncSetAttribute(k_idfth, cudaFuncAttributeMaxDynamicSharedMemorySize, 73728);

    void *p0, *p1;
    cudaGetSymbolAddress(&p0, g_h0);
    cudaGetSymbolAddress(&p1, g_h1);
    float* hb[2] = {(float*)p0, (float*)p1};

    k_twiddle<<<32, 256>>>();
    k_wt<<<(NLAY * 512 * WID * WID) / 256, 256>>>(w1r, w1i, w2r, w2i);
    k_fc0<<<NPIX / 256, 256>>>(x, fc0w, fc0b);

    for (int l = 0; l < NLAY; l++) {
        const float* hi = hb[l & 1];
        float*       ho = hb[(l + 1) & 1];
        k_dftw<<<1024, 256, 49280>>>(hi);
        k_dfth<<<1024, 256, 98304>>>();
        k_mix<<<512, 256>>>(l);
        k_idfth<<<1024, 256, 73728>>>();
        k_fused<<<4096, 256>>>(hi, ho, pww + (size_t)l * WID * WID,
                               pwb + (size_t)l * WID, (l < NLAY - 1) ? 1 : 0);
    }
    k_final<<<4096, 256>>>(hb[0], out, fc1w, fc1b, fc2w, fc2b);
}